// round 14
// baseline (speedup 1.0000x reference)
#include <cuda_runtime.h>
#include <cuda_fp16.h>

#define B_ 8
#define H_ 64
#define W_ 64
#define C_ 256
#define N_ 512
#define POOL_ 7
#define NPOS (POOL_ * POOL_)   // 49
#define NBOX (B_ * N_)         // 4096
#define FM_ELEMS (B_ * H_ * W_ * C_)   // 8388608
#define NCELL 512              // 8 images x 8x8 cells
#define NSM 152                // GB300 SM count

// fp16 copy of the feature map (16.8 MB static scratch).
__device__ __half g_fmh[FM_ELEMS];
// counting-sort scratch
__device__ int g_cnt[NCELL];
__device__ int g_cell[NBOX];
__device__ int g_rank[NBOX];
__device__ int g_celloff[NCELL];
__device__ int g_order[NBOX];

__global__ void __launch_bounds__(256) fm_convert_kernel(const float* __restrict__ fm) {
    const int i = blockIdx.x * blockDim.x + threadIdx.x;   // over FM_ELEMS/4
    const float4 v = __ldg((const float4*)fm + i);
    const __half2 h01 = __floats2half2_rn(v.x, v.y);
    const __half2 h23 = __floats2half2_rn(v.z, v.w);
    uint2 u;
    u.x = *(const unsigned int*)&h01;
    u.y = *(const unsigned int*)&h23;
    ((uint2*)g_fmh)[i] = u;
}

// ---- counting sort of boxes by (image, 8x8 cell of center) ----
__global__ void sort_zero_kernel() { g_cnt[threadIdx.x] = 0; }

__global__ void sort_count_kernel(const float* __restrict__ boxes) {
    const int i = blockIdx.x * blockDim.x + threadIdx.x;   // 0..4095
    const float4 bx = __ldg((const float4*)(boxes + (size_t)i * 4));
    const float cxf = 0.5f * (bx.x + bx.z) * 63.f;         // center in [0,63]
    const float cyf = 0.5f * (bx.y + bx.w) * 63.f;
    const int cx = min(max((int)cxf, 0), 63) >> 3;         // 0..7
    const int cy = min(max((int)cyf, 0), 63) >> 3;
    const int cell = ((i >> 9) << 6) | (cy << 3) | cx;     // image*64 + cy*8 + cx
    g_cell[i] = cell;
    g_rank[i] = atomicAdd(&g_cnt[cell], 1);
}

__global__ void sort_scan_kernel() {      // 1 block, 512 threads
    __shared__ int s[NCELL];
    const int t = threadIdx.x;
    const int orig = g_cnt[t];
    s[t] = orig;
    __syncthreads();
    for (int d = 1; d < NCELL; d <<= 1) {
        int v = (t >= d) ? s[t - d] : 0;
        __syncthreads();
        s[t] += v;
        __syncthreads();
    }
    g_celloff[t] = s[t] - orig;           // exclusive prefix
}

__global__ void sort_scatter_kernel() {
    const int i = blockIdx.x * blockDim.x + threadIdx.x;   // 0..4095
    g_order[g_celloff[g_cell[i]] + g_rank[i]] = i;
}

// ---- gather ----
__device__ __forceinline__ float4 blend4(uint2 utl, uint2 utr, uint2 ubl, uint2 ubr, float4 w) {
    const float2 tl01 = __half22float2(*(const __half2*)&utl.x);
    const float2 tl23 = __half22float2(*(const __half2*)&utl.y);
    const float2 tr01 = __half22float2(*(const __half2*)&utr.x);
    const float2 tr23 = __half22float2(*(const __half2*)&utr.y);
    const float2 bl01 = __half22float2(*(const __half2*)&ubl.x);
    const float2 bl23 = __half22float2(*(const __half2*)&ubl.y);
    const float2 br01 = __half22float2(*(const __half2*)&ubr.x);
    const float2 br23 = __half22float2(*(const __half2*)&ubr.y);
    float4 o;
    o.x = fmaf(br01.x, w.w, fmaf(bl01.x, w.z, fmaf(tr01.x, w.y, tl01.x * w.x)));
    o.y = fmaf(br01.y, w.w, fmaf(bl01.y, w.z, fmaf(tr01.y, w.y, tl01.y * w.x)));
    o.z = fmaf(br23.x, w.w, fmaf(bl23.x, w.z, fmaf(tr23.x, w.y, tl23.x * w.x)));
    o.w = fmaf(br23.y, w.w, fmaf(bl23.y, w.z, fmaf(tr23.y, w.y, tl23.y * w.x)));
    return o;
}

__global__ void __launch_bounds__(448, 4) roi_align_fused(const float* __restrict__ boxes,
                                                          float* __restrict__ out) {
    __shared__ int4   s_off[NPOS];
    __shared__ float4 s_w[NPOS];

    // bid -> sorted-order index such that all bids with equal (bid % NSM)
    // (i.e., CTAs placed on the SAME SM by the classic LUT) get a contiguous
    // run of spatially-sorted boxes.
    const int bid = blockIdx.x;
    const int s = bid % NSM;            // SM slot
    const int t = bid / NSM;            // wave index (0..26)
    const int j = s * 26 + min(s, NBOX - NSM * 26) + t;   // NBOX-NSM*26 = 144
    const int box = g_order[j];

    const int tid = threadIdx.y * 64 + threadIdx.x;

    if (tid < NPOS) {
        const int b  = box >> 9;
        const int py = tid / POOL_;
        const int px = tid - py * POOL_;

        const float4 bx = __ldg((const float4*)(boxes + (size_t)box * 4));
        const float x1 = bx.x, y1 = bx.y, x2 = bx.z, y2 = bx.w;

        const float ys = y1 * (H_ - 1) + (float)py * ((y2 - y1) * (H_ - 1) / (POOL_ - 1));
        const float xs = x1 * (W_ - 1) + (float)px * ((x2 - x1) * (W_ - 1) / (POOL_ - 1));

        const float yf = floorf(ys);
        const float xf = floorf(xs);
        const float fy = ys - yf;
        const float fx = xs - xf;

        int yt = (int)yf, xl = (int)xf;
        int yb = yt + 1,  xr = xl + 1;
        yt = min(max(yt, 0), H_ - 1);
        yb = min(max(yb, 0), H_ - 1);
        xl = min(max(xl, 0), W_ - 1);
        xr = min(max(xr, 0), W_ - 1);

        // normalized boxes in [0,1] => samples always in-range; mask always true.
        s_w[tid] = make_float4((1.f - fy) * (1.f - fx),
                               (1.f - fy) * fx,
                               fy * (1.f - fx),
                               fy * fx);

        const int base = b * (H_ * W_ * C_);
        s_off[tid] = make_int4(base + (yt * W_ + xl) * C_,
                               base + (yt * W_ + xr) * C_,
                               base + (yb * W_ + xl) * C_,
                               base + (yb * W_ + xr) * C_);
    }
    __syncthreads();

    const int lane4 = threadIdx.x;                      // 64 lanes x 4 channels
    float* obase = out + (size_t)box * NPOS * C_ + lane4 * 4;

    // 7 rows: 3 paired iterations (rows k and k+4) + 1 single (row 3).
    #pragma unroll
    for (int k = 0; k < 3; k++) {
        const int posA = k * POOL_ + threadIdx.y;             // rows 0,1,2
        const int posB = (k + 4) * POOL_ + threadIdx.y;       // rows 4,5,6

        const int4 offA = s_off[posA];
        const int4 offB = s_off[posB];

        const uint2 atl = __ldg((const uint2*)(g_fmh + offA.x) + lane4);
        const uint2 atr = __ldg((const uint2*)(g_fmh + offA.y) + lane4);
        const uint2 abl = __ldg((const uint2*)(g_fmh + offA.z) + lane4);
        const uint2 abr = __ldg((const uint2*)(g_fmh + offA.w) + lane4);
        const uint2 btl = __ldg((const uint2*)(g_fmh + offB.x) + lane4);
        const uint2 btr = __ldg((const uint2*)(g_fmh + offB.y) + lane4);
        const uint2 bbl = __ldg((const uint2*)(g_fmh + offB.z) + lane4);
        const uint2 bbr = __ldg((const uint2*)(g_fmh + offB.w) + lane4);

        const float4 oA = blend4(atl, atr, abl, abr, s_w[posA]);
        const float4 oB = blend4(btl, btr, bbl, bbr, s_w[posB]);

        __stcs((float4*)(obase + (size_t)posA * C_), oA);
        __stcs((float4*)(obase + (size_t)posB * C_), oB);
    }
    {
        const int pos = 3 * POOL_ + threadIdx.y;              // row 3
        const int4 offs = s_off[pos];
        const uint2 tl = __ldg((const uint2*)(g_fmh + offs.x) + lane4);
        const uint2 tr = __ldg((const uint2*)(g_fmh + offs.y) + lane4);
        const uint2 bl = __ldg((const uint2*)(g_fmh + offs.z) + lane4);
        const uint2 br = __ldg((const uint2*)(g_fmh + offs.w) + lane4);
        const float4 o = blend4(tl, tr, bl, br, s_w[pos]);
        __stcs((float4*)(obase + (size_t)pos * C_), o);
    }
}

extern "C" void kernel_launch(void* const* d_in, const int* in_sizes, int n_in,
                              void* d_out, int out_size) {
    const float* fm    = (const float*)d_in[0];   // [8,64,64,256] fp32
    const float* boxes = (const float*)d_in[1];   // [8,512,4]
    float* out = (float*)d_out;                   // [8,512,7,7,256] fp32

    // spatial counting sort of boxes (tiny kernels)
    sort_zero_kernel<<<1, NCELL>>>();
    sort_count_kernel<<<NBOX / 256, 256>>>(boxes);
    sort_scan_kernel<<<1, NCELL>>>();
    sort_scatter_kernel<<<NBOX / 256, 256>>>();

    // fp32 -> fp16 feature-map copy (~6 us, HBM-floor bound)
    fm_convert_kernel<<<FM_ELEMS / 4 / 256, 256>>>(fm);

    // gather + bilinear blend, spatially-clustered per SM
    dim3 block(64, POOL_);      // 448 threads
    roi_align_fused<<<NBOX, block>>>(boxes, out);
}

// round 15
// speedup vs baseline: 1.0048x; 1.0048x over previous
#include <cuda_runtime.h>
#include <cuda_fp16.h>

#define B_ 8
#define H_ 64
#define W_ 64
#define C_ 256
#define N_ 512
#define POOL_ 7
#define NPOS (POOL_ * POOL_)   // 49
#define NBOX (B_ * N_)         // 4096
#define FM_ELEMS (B_ * H_ * W_ * C_)   // 8388608
#define NCHUNK 4
#define F4_PER_CHUNK (FM_ELEMS / 4 / NCHUNK)   // 524288 float4 per chunk
#define BOX_PER_CHUNK (NBOX / NCHUNK)          // 1024

// fp16 copy of the feature map (16.8 MB static scratch — no allocation).
__device__ __half g_fmh[FM_ELEMS];

__global__ void __launch_bounds__(256) fm_convert_chunk(const float* __restrict__ fm,
                                                        int base4) {
    // let the next kernel in the PDL chain launch immediately
    asm volatile("griddepcontrol.launch_dependents;");
    const int i = base4 + blockIdx.x * blockDim.x + threadIdx.x;   // float4 index
    const float4 v = __ldg((const float4*)fm + i);
    const __half2 h01 = __floats2half2_rn(v.x, v.y);
    const __half2 h23 = __floats2half2_rn(v.z, v.w);
    uint2 u;
    u.x = *(const unsigned int*)&h01;
    u.y = *(const unsigned int*)&h23;
    ((uint2*)g_fmh)[i] = u;
}

__device__ __forceinline__ float4 blend4(uint2 utl, uint2 utr, uint2 ubl, uint2 ubr, float4 w) {
    const float2 tl01 = __half22float2(*(const __half2*)&utl.x);
    const float2 tl23 = __half22float2(*(const __half2*)&utl.y);
    const float2 tr01 = __half22float2(*(const __half2*)&utr.x);
    const float2 tr23 = __half22float2(*(const __half2*)&utr.y);
    const float2 bl01 = __half22float2(*(const __half2*)&ubl.x);
    const float2 bl23 = __half22float2(*(const __half2*)&ubl.y);
    const float2 br01 = __half22float2(*(const __half2*)&ubr.x);
    const float2 br23 = __half22float2(*(const __half2*)&ubr.y);
    float4 o;
    o.x = fmaf(br01.x, w.w, fmaf(bl01.x, w.z, fmaf(tr01.x, w.y, tl01.x * w.x)));
    o.y = fmaf(br01.y, w.w, fmaf(bl01.y, w.z, fmaf(tr01.y, w.y, tl01.y * w.x)));
    o.z = fmaf(br23.x, w.w, fmaf(bl23.x, w.z, fmaf(tr23.x, w.y, tl23.x * w.x)));
    o.w = fmaf(br23.y, w.w, fmaf(bl23.y, w.z, fmaf(tr23.y, w.y, tl23.y * w.x)));
    return o;
}

__global__ void __launch_bounds__(448, 4) roi_gather_chunk(const float* __restrict__ boxes,
                                                           float* __restrict__ out,
                                                           int box_base) {
    // release the next convert chunk right away (it has no data dep on us)
    asm volatile("griddepcontrol.launch_dependents;");

    __shared__ int4   s_off[NPOS];
    __shared__ float4 s_w[NPOS];

    const int box = box_base + blockIdx.x;              // within this image-pair chunk
    const int tid = threadIdx.y * 64 + threadIdx.x;

    // ---- meta prologue: reads only `boxes`, safe before griddepcontrol.wait ----
    if (tid < NPOS) {
        const int b  = box >> 9;
        const int py = tid / POOL_;
        const int px = tid - py * POOL_;

        const float4 bx = __ldg((const float4*)(boxes + (size_t)box * 4));
        const float x1 = bx.x, y1 = bx.y, x2 = bx.z, y2 = bx.w;

        const float ys = y1 * (H_ - 1) + (float)py * ((y2 - y1) * (H_ - 1) / (POOL_ - 1));
        const float xs = x1 * (W_ - 1) + (float)px * ((x2 - x1) * (W_ - 1) / (POOL_ - 1));

        const float yf = floorf(ys);
        const float xf = floorf(xs);
        const float fy = ys - yf;
        const float fx = xs - xf;

        int yt = (int)yf, xl = (int)xf;
        int yb = yt + 1,  xr = xl + 1;
        yt = min(max(yt, 0), H_ - 1);
        yb = min(max(yb, 0), H_ - 1);
        xl = min(max(xl, 0), W_ - 1);
        xr = min(max(xr, 0), W_ - 1);

        // normalized boxes in [0,1] => samples always in-range; mask always true.
        s_w[tid] = make_float4((1.f - fy) * (1.f - fx),
                               (1.f - fy) * fx,
                               fy * (1.f - fx),
                               fy * fx);

        const int base = b * (H_ * W_ * C_);
        s_off[tid] = make_int4(base + (yt * W_ + xl) * C_,
                               base + (yt * W_ + xr) * C_,
                               base + (yb * W_ + xl) * C_,
                               base + (yb * W_ + xr) * C_);
    }
    __syncthreads();

    // wait for OUR convert chunk (the immediately preceding kernel) to complete
    asm volatile("griddepcontrol.wait;");

    const int lane4 = threadIdx.x;                      // 64 lanes x 4 channels
    float* obase = out + (size_t)box * NPOS * C_ + lane4 * 4;

    // 7 rows: 3 paired iterations (rows k and k+4) + 1 single (row 3).
    #pragma unroll
    for (int k = 0; k < 3; k++) {
        const int posA = k * POOL_ + threadIdx.y;             // rows 0,1,2
        const int posB = (k + 4) * POOL_ + threadIdx.y;       // rows 4,5,6

        const int4 offA = s_off[posA];
        const int4 offB = s_off[posB];

        const uint2 atl = __ldg((const uint2*)(g_fmh + offA.x) + lane4);
        const uint2 atr = __ldg((const uint2*)(g_fmh + offA.y) + lane4);
        const uint2 abl = __ldg((const uint2*)(g_fmh + offA.z) + lane4);
        const uint2 abr = __ldg((const uint2*)(g_fmh + offA.w) + lane4);
        const uint2 btl = __ldg((const uint2*)(g_fmh + offB.x) + lane4);
        const uint2 btr = __ldg((const uint2*)(g_fmh + offB.y) + lane4);
        const uint2 bbl = __ldg((const uint2*)(g_fmh + offB.z) + lane4);
        const uint2 bbr = __ldg((const uint2*)(g_fmh + offB.w) + lane4);

        const float4 oA = blend4(atl, atr, abl, abr, s_w[posA]);
        const float4 oB = blend4(btl, btr, bbl, bbr, s_w[posB]);

        __stcs((float4*)(obase + (size_t)posA * C_), oA);
        __stcs((float4*)(obase + (size_t)posB * C_), oB);
    }
    {
        const int pos = 3 * POOL_ + threadIdx.y;              // row 3
        const int4 offs = s_off[pos];
        const uint2 tl = __ldg((const uint2*)(g_fmh + offs.x) + lane4);
        const uint2 tr = __ldg((const uint2*)(g_fmh + offs.y) + lane4);
        const uint2 bl = __ldg((const uint2*)(g_fmh + offs.z) + lane4);
        const uint2 br = __ldg((const uint2*)(g_fmh + offs.w) + lane4);
        const float4 o = blend4(tl, tr, bl, br, s_w[pos]);
        __stcs((float4*)(obase + (size_t)pos * C_), o);
    }
}

extern "C" void kernel_launch(void* const* d_in, const int* in_sizes, int n_in,
                              void* d_out, int out_size) {
    const float* fm    = (const float*)d_in[0];   // [8,64,64,256] fp32
    const float* boxes = (const float*)d_in[1];   // [8,512,4]
    float* out = (float*)d_out;                   // [8,512,7,7,256] fp32

    cudaLaunchAttribute pdl[1];
    pdl[0].id = cudaLaunchAttributeProgrammaticStreamSerialization;
    pdl[0].val.programmaticStreamSerializationAllowed = 1;

    for (int ck = 0; ck < NCHUNK; ck++) {
        // convert chunk ck (images 2ck, 2ck+1)
        {
            cudaLaunchConfig_t cfg = {};
            cfg.gridDim  = dim3(F4_PER_CHUNK / 256);
            cfg.blockDim = dim3(256);
            cfg.stream   = 0;
            if (ck > 0) { cfg.attrs = pdl; cfg.numAttrs = 1; }   // gated on prev gather's trigger
            cudaLaunchKernelEx(&cfg, fm_convert_chunk, fm, ck * F4_PER_CHUNK);
        }
        // gather chunk ck (boxes of images 2ck, 2ck+1)
        {
            cudaLaunchConfig_t cfg = {};
            cfg.gridDim  = dim3(BOX_PER_CHUNK);
            cfg.blockDim = dim3(64, POOL_);
            cfg.stream   = 0;
            cfg.attrs = pdl; cfg.numAttrs = 1;                   // waits on its convert via griddepcontrol.wait
            cudaLaunchKernelEx(&cfg, roi_gather_chunk, boxes, out, ck * BOX_PER_CHUNK);
        }
    }
}

// round 16
// speedup vs baseline: 1.1121x; 1.1069x over previous
#include <cuda_runtime.h>
#include <cuda_fp16.h>

#define B_ 8
#define H_ 64
#define W_ 64
#define C_ 256
#define N_ 512
#define POOL_ 7
#define NPOS (POOL_ * POOL_)   // 49
#define NBOX (B_ * N_)         // 4096
#define FM_ELEMS (B_ * H_ * W_ * C_)   // 8388608

// fp16 copy of the feature map (16.8 MB static scratch — no allocation).
__device__ __half g_fmh[FM_ELEMS];

__global__ void __launch_bounds__(256) fm_convert_kernel(const float* __restrict__ fm) {
    // Release the gather immediately: its blocks can schedule, run their meta
    // prologue, and park at griddepcontrol.wait while we stream-convert.
    asm volatile("griddepcontrol.launch_dependents;");
    const int i = blockIdx.x * blockDim.x + threadIdx.x;   // over FM_ELEMS/4
    const float4 v = __ldcs((const float4*)fm + i);        // streaming: fm is dead after this
    const __half2 h01 = __floats2half2_rn(v.x, v.y);
    const __half2 h23 = __floats2half2_rn(v.z, v.w);
    uint2 u;
    u.x = *(const unsigned int*)&h01;
    u.y = *(const unsigned int*)&h23;
    ((uint2*)g_fmh)[i] = u;                                 // default st: keep L2-resident
}

__device__ __forceinline__ float4 blend4(uint2 utl, uint2 utr, uint2 ubl, uint2 ubr, float4 w) {
    const float2 tl01 = __half22float2(*(const __half2*)&utl.x);
    const float2 tl23 = __half22float2(*(const __half2*)&utl.y);
    const float2 tr01 = __half22float2(*(const __half2*)&utr.x);
    const float2 tr23 = __half22float2(*(const __half2*)&utr.y);
    const float2 bl01 = __half22float2(*(const __half2*)&ubl.x);
    const float2 bl23 = __half22float2(*(const __half2*)&ubl.y);
    const float2 br01 = __half22float2(*(const __half2*)&ubr.x);
    const float2 br23 = __half22float2(*(const __half2*)&ubr.y);
    float4 o;
    o.x = fmaf(br01.x, w.w, fmaf(bl01.x, w.z, fmaf(tr01.x, w.y, tl01.x * w.x)));
    o.y = fmaf(br01.y, w.w, fmaf(bl01.y, w.z, fmaf(tr01.y, w.y, tl01.y * w.x)));
    o.z = fmaf(br23.x, w.w, fmaf(bl23.x, w.z, fmaf(tr23.x, w.y, tl23.x * w.x)));
    o.w = fmaf(br23.y, w.w, fmaf(bl23.y, w.z, fmaf(tr23.y, w.y, tl23.y * w.x)));
    return o;
}

__global__ void __launch_bounds__(448, 4) roi_align_fused(const float* __restrict__ boxes,
                                                          float* __restrict__ out) {
    __shared__ int4   s_off[NPOS];
    __shared__ float4 s_w[NPOS];

    const int box = blockIdx.x;                         // 0..4095
    const int tid = threadIdx.y * 64 + threadIdx.x;

    // ---- meta prologue: reads only `boxes`; runs while convert is in flight ----
    if (tid < NPOS) {
        const int b  = box >> 9;
        const int py = tid / POOL_;
        const int px = tid - py * POOL_;

        const float4 bx = __ldg((const float4*)(boxes + (size_t)box * 4));
        const float x1 = bx.x, y1 = bx.y, x2 = bx.z, y2 = bx.w;

        const float ys = y1 * (H_ - 1) + (float)py * ((y2 - y1) * (H_ - 1) / (POOL_ - 1));
        const float xs = x1 * (W_ - 1) + (float)px * ((x2 - x1) * (W_ - 1) / (POOL_ - 1));

        const float yf = floorf(ys);
        const float xf = floorf(xs);
        const float fy = ys - yf;
        const float fx = xs - xf;

        int yt = (int)yf, xl = (int)xf;
        int yb = yt + 1,  xr = xl + 1;
        yt = min(max(yt, 0), H_ - 1);
        yb = min(max(yb, 0), H_ - 1);
        xl = min(max(xl, 0), W_ - 1);
        xr = min(max(xr, 0), W_ - 1);

        // normalized boxes in [0,1] => samples always in-range; mask always true.
        s_w[tid] = make_float4((1.f - fy) * (1.f - fx),
                               (1.f - fy) * fx,
                               fy * (1.f - fx),
                               fy * fx);

        const int base = b * (H_ * W_ * C_);
        s_off[tid] = make_int4(base + (yt * W_ + xl) * C_,
                               base + (yt * W_ + xr) * C_,
                               base + (yb * W_ + xl) * C_,
                               base + (yb * W_ + xr) * C_);
    }
    __syncthreads();

    // Block until the convert grid has fully completed.
    asm volatile("griddepcontrol.wait;");

    const int lane4 = threadIdx.x;                      // 64 lanes x 4 channels
    float* obase = out + (size_t)box * NPOS * C_ + lane4 * 4;

    // 7 rows: 3 paired iterations (rows k and k+4) + 1 single (row 3).
    #pragma unroll
    for (int k = 0; k < 3; k++) {
        const int posA = k * POOL_ + threadIdx.y;             // rows 0,1,2
        const int posB = (k + 4) * POOL_ + threadIdx.y;       // rows 4,5,6

        const int4 offA = s_off[posA];
        const int4 offB = s_off[posB];

        // 8 independent LDG.64 in flight per thread
        const uint2 atl = __ldg((const uint2*)(g_fmh + offA.x) + lane4);
        const uint2 atr = __ldg((const uint2*)(g_fmh + offA.y) + lane4);
        const uint2 abl = __ldg((const uint2*)(g_fmh + offA.z) + lane4);
        const uint2 abr = __ldg((const uint2*)(g_fmh + offA.w) + lane4);
        const uint2 btl = __ldg((const uint2*)(g_fmh + offB.x) + lane4);
        const uint2 btr = __ldg((const uint2*)(g_fmh + offB.y) + lane4);
        const uint2 bbl = __ldg((const uint2*)(g_fmh + offB.z) + lane4);
        const uint2 bbr = __ldg((const uint2*)(g_fmh + offB.w) + lane4);

        const float4 oA = blend4(atl, atr, abl, abr, s_w[posA]);
        const float4 oB = blend4(btl, btr, bbl, bbr, s_w[posB]);

        __stcs((float4*)(obase + (size_t)posA * C_), oA);
        __stcs((float4*)(obase + (size_t)posB * C_), oB);
    }
    {
        const int pos = 3 * POOL_ + threadIdx.y;              // row 3
        const int4 offs = s_off[pos];
        const uint2 tl = __ldg((const uint2*)(g_fmh + offs.x) + lane4);
        const uint2 tr = __ldg((const uint2*)(g_fmh + offs.y) + lane4);
        const uint2 bl = __ldg((const uint2*)(g_fmh + offs.z) + lane4);
        const uint2 br = __ldg((const uint2*)(g_fmh + offs.w) + lane4);
        const float4 o = blend4(tl, tr, bl, br, s_w[pos]);
        __stcs((float4*)(obase + (size_t)pos * C_), o);
    }
}

extern "C" void kernel_launch(void* const* d_in, const int* in_sizes, int n_in,
                              void* d_out, int out_size) {
    const float* fm    = (const float*)d_in[0];   // [8,64,64,256] fp32
    const float* boxes = (const float*)d_in[1];   // [8,512,4]
    float* out = (float*)d_out;                   // [8,512,7,7,256] fp32

    // 1) fp32 -> fp16 feature-map copy (monolithic, DRAM-floor ~6.3 us)
    fm_convert_kernel<<<FM_ELEMS / 4 / 256, 256>>>(fm);

    // 2) gather: monolithic grid, launched programmatically-early so its ramp
    //    (scheduling + smem meta) overlaps the convert.
    cudaLaunchAttribute pdl[1];
    pdl[0].id = cudaLaunchAttributeProgrammaticStreamSerialization;
    pdl[0].val.programmaticStreamSerializationAllowed = 1;

    cudaLaunchConfig_t cfg = {};
    cfg.gridDim  = dim3(NBOX);
    cfg.blockDim = dim3(64, POOL_);     // 448 threads
    cfg.stream   = 0;
    cfg.attrs    = pdl;
    cfg.numAttrs = 1;
    cudaLaunchKernelEx(&cfg, roi_align_fused, boxes, out);
}

// round 17
// speedup vs baseline: 1.1331x; 1.0188x over previous
#include <cuda_runtime.h>
#include <cuda_fp16.h>

#define B_ 8
#define H_ 64
#define W_ 64
#define C_ 256
#define N_ 512
#define POOL_ 7
#define NPOS (POOL_ * POOL_)   // 49
#define NBOX (B_ * N_)         // 4096
#define FM_ELEMS (B_ * H_ * W_ * C_)   // 8388608

// fp16 copy of the feature map (16.8 MB static scratch — no allocation).
__device__ __half g_fmh[FM_ELEMS];

__global__ void __launch_bounds__(256) fm_convert_kernel(const float* __restrict__ fm) {
    const int i = blockIdx.x * blockDim.x + threadIdx.x;   // over FM_ELEMS/4
    const float4 v = __ldcs((const float4*)fm + i);        // streaming: fm is dead after this
    const __half2 h01 = __floats2half2_rn(v.x, v.y);
    const __half2 h23 = __floats2half2_rn(v.z, v.w);
    uint2 u;
    u.x = *(const unsigned int*)&h01;
    u.y = *(const unsigned int*)&h23;
    ((uint2*)g_fmh)[i] = u;
}

__device__ __forceinline__ float4 blend4(uint2 utl, uint2 utr, uint2 ubl, uint2 ubr, float4 w) {
    const float2 tl01 = __half22float2(*(const __half2*)&utl.x);
    const float2 tl23 = __half22float2(*(const __half2*)&utl.y);
    const float2 tr01 = __half22float2(*(const __half2*)&utr.x);
    const float2 tr23 = __half22float2(*(const __half2*)&utr.y);
    const float2 bl01 = __half22float2(*(const __half2*)&ubl.x);
    const float2 bl23 = __half22float2(*(const __half2*)&ubl.y);
    const float2 br01 = __half22float2(*(const __half2*)&ubr.x);
    const float2 br23 = __half22float2(*(const __half2*)&ubr.y);
    float4 o;
    o.x = fmaf(br01.x, w.w, fmaf(bl01.x, w.z, fmaf(tr01.x, w.y, tl01.x * w.x)));
    o.y = fmaf(br01.y, w.w, fmaf(bl01.y, w.z, fmaf(tr01.y, w.y, tl01.y * w.x)));
    o.z = fmaf(br23.x, w.w, fmaf(bl23.x, w.z, fmaf(tr23.x, w.y, tl23.x * w.x)));
    o.w = fmaf(br23.y, w.w, fmaf(bl23.y, w.z, fmaf(tr23.y, w.y, tl23.y * w.x)));
    return o;
}

__global__ void __launch_bounds__(448, 4) roi_align_fused(const float* __restrict__ boxes,
                                                          float* __restrict__ out) {
    __shared__ int4   s_off[NPOS];
    __shared__ float4 s_w[NPOS];

    const int box = blockIdx.x;                         // 0..4095
    const int tid = threadIdx.y * 64 + threadIdx.x;

    if (tid < NPOS) {
        const int b  = box >> 9;
        const int py = tid / POOL_;
        const int px = tid - py * POOL_;

        const float4 bx = __ldg((const float4*)(boxes + (size_t)box * 4));
        const float x1 = bx.x, y1 = bx.y, x2 = bx.z, y2 = bx.w;

        const float ys = y1 * (H_ - 1) + (float)py * ((y2 - y1) * (H_ - 1) / (POOL_ - 1));
        const float xs = x1 * (W_ - 1) + (float)px * ((x2 - x1) * (W_ - 1) / (POOL_ - 1));

        const float yf = floorf(ys);
        const float xf = floorf(xs);
        const float fy = ys - yf;
        const float fx = xs - xf;

        int yt = (int)yf, xl = (int)xf;
        int yb = yt + 1,  xr = xl + 1;
        yt = min(max(yt, 0), H_ - 1);
        yb = min(max(yb, 0), H_ - 1);
        xl = min(max(xl, 0), W_ - 1);
        xr = min(max(xr, 0), W_ - 1);

        // normalized boxes in [0,1] => samples always in-range; mask always true.
        s_w[tid] = make_float4((1.f - fy) * (1.f - fx),
                               (1.f - fy) * fx,
                               fy * (1.f - fx),
                               fy * fx);

        const int base = b * (H_ * W_ * C_);
        s_off[tid] = make_int4(base + (yt * W_ + xl) * C_,
                               base + (yt * W_ + xr) * C_,
                               base + (yb * W_ + xl) * C_,
                               base + (yb * W_ + xr) * C_);
    }
    __syncthreads();

    const int lane4 = threadIdx.x;                      // 64 lanes x 4 channels
    float* obase = out + (size_t)box * NPOS * C_ + lane4 * 4;

    // 7 rows: 3 paired iterations (rows k and k+4) + 1 single (row 3).
    #pragma unroll
    for (int k = 0; k < 3; k++) {
        const int posA = k * POOL_ + threadIdx.y;             // rows 0,1,2
        const int posB = (k + 4) * POOL_ + threadIdx.y;       // rows 4,5,6

        const int4 offA = s_off[posA];
        const int4 offB = s_off[posB];

        // 8 independent LDG.64 in flight per thread
        const uint2 atl = __ldg((const uint2*)(g_fmh + offA.x) + lane4);
        const uint2 atr = __ldg((const uint2*)(g_fmh + offA.y) + lane4);
        const uint2 abl = __ldg((const uint2*)(g_fmh + offA.z) + lane4);
        const uint2 abr = __ldg((const uint2*)(g_fmh + offA.w) + lane4);
        const uint2 btl = __ldg((const uint2*)(g_fmh + offB.x) + lane4);
        const uint2 btr = __ldg((const uint2*)(g_fmh + offB.y) + lane4);
        const uint2 bbl = __ldg((const uint2*)(g_fmh + offB.z) + lane4);
        const uint2 bbr = __ldg((const uint2*)(g_fmh + offB.w) + lane4);

        const float4 oA = blend4(atl, atr, abl, abr, s_w[posA]);
        const float4 oB = blend4(btl, btr, bbl, bbr, s_w[posB]);

        __stcs((float4*)(obase + (size_t)posA * C_), oA);
        __stcs((float4*)(obase + (size_t)posB * C_), oB);
    }
    {
        const int pos = 3 * POOL_ + threadIdx.y;              // row 3
        const int4 offs = s_off[pos];
        const uint2 tl = __ldg((const uint2*)(g_fmh + offs.x) + lane4);
        const uint2 tr = __ldg((const uint2*)(g_fmh + offs.y) + lane4);
        const uint2 bl = __ldg((const uint2*)(g_fmh + offs.z) + lane4);
        const uint2 br = __ldg((const uint2*)(g_fmh + offs.w) + lane4);
        const float4 o = blend4(tl, tr, bl, br, s_w[pos]);
        __stcs((float4*)(obase + (size_t)pos * C_), o);
    }
}

extern "C" void kernel_launch(void* const* d_in, const int* in_sizes, int n_in,
                              void* d_out, int out_size) {
    const float* fm    = (const float*)d_in[0];   // [8,64,64,256] fp32
    const float* boxes = (const float*)d_in[1];   // [8,512,4]
    float* out = (float*)d_out;                   // [8,512,7,7,256] fp32

    // 1) fp32 -> fp16 feature-map copy (DRAM-floor ~6.3 us)
    fm_convert_kernel<<<FM_ELEMS / 4 / 256, 256>>>(fm);

    // 2) gather with g_fmh pinned persisting in L2 for the duration of the launch
    void* fmh_ptr = nullptr;
    cudaGetSymbolAddress(&fmh_ptr, g_fmh);

    cudaLaunchAttribute attrs[1];
    attrs[0].id = cudaLaunchAttributeAccessPolicyWindow;
    attrs[0].val.accessPolicyWindow.base_ptr  = fmh_ptr;
    attrs[0].val.accessPolicyWindow.num_bytes = FM_ELEMS * sizeof(__half);  // 16.8 MB
    attrs[0].val.accessPolicyWindow.hitRatio  = 1.0f;
    attrs[0].val.accessPolicyWindow.hitProp   = cudaAccessPropertyPersisting;
    attrs[0].val.accessPolicyWindow.missProp  = cudaAccessPropertyNormal;

    cudaLaunchConfig_t cfg = {};
    cfg.gridDim  = dim3(NBOX);
    cfg.blockDim = dim3(64, POOL_);     // 448 threads
    cfg.stream   = 0;
    cfg.attrs    = attrs;
    cfg.numAttrs = 1;
    cudaLaunchKernelEx(&cfg, roi_align_fused, boxes, out);
}